// round 15
// baseline (speedup 1.0000x reference)
#include <cuda_runtime.h>
#include <cuda_bf16.h>
#include <math.h>

#define BQ 2
#define SQ 1024
#define HQ 1024
#define NHQ 16
#define HDQ 64
#define FFQ 4096
#define LQ 4
#define VQ 32000
#define H3 (3*HQ)

typedef unsigned int u32;
typedef unsigned long long u64;
typedef __nv_bfloat16 bf16;

// ---------------- scratch (static device globals; no allocation) ----------------
__device__ float g_h [BQ*SQ*HQ];
__device__ float g_t [BQ*SQ*HQ];
__device__ float g_bqkv[LQ*H3];                          // concatenated qkv bias
__device__ bf16 g_hs  [2LL*BQ*SQ*HQ];                    // split activations (hi plane, lo plane)
__device__ bf16 g_qkvs[2LL*BQ*SQ*H3];                    // merged qkv output (split)
__device__ bf16 g_os  [2LL*BQ*SQ*HQ];
__device__ bf16 g_fs  [2LL*BQ*SQ*FFQ];
__device__ bf16 g_wqkv[2LL*LQ*HQ*H3];                    // merged split qkv weights
__device__ bf16 g_wos [2LL*LQ*HQ*HQ];
__device__ bf16 g_w1s [2LL*LQ*HQ*FFQ];
__device__ bf16 g_w2s [2LL*LQ*FFQ*HQ];
__device__ bf16 g_fws [2LL*(long long)VQ*HQ];

// ---------------- helpers ----------------
__device__ __forceinline__ void split2(float x, float y, u32& hi, u32& lo) {
    __nv_bfloat162 h2 = __floats2bfloat162_rn(x, y);
    float2 bk = __bfloat1622float2(h2);
    __nv_bfloat162 l2 = __floats2bfloat162_rn(x - bk.x, y - bk.y);
    hi = *reinterpret_cast<u32*>(&h2);
    lo = *reinterpret_cast<u32*>(&l2);
}
__device__ __forceinline__ void cpa16(u32 saddr, const void* gaddr) {
    asm volatile("cp.async.cg.shared.global [%0], [%1], 16;" :: "r"(saddr), "l"(gaddr));
}
__device__ __forceinline__ void ldm4(u32* d, u32 a) {
    asm volatile("ldmatrix.sync.aligned.m8n8.x4.shared.b16 {%0,%1,%2,%3}, [%4];"
                 : "=r"(d[0]), "=r"(d[1]), "=r"(d[2]), "=r"(d[3]) : "r"(a));
}
__device__ __forceinline__ void ldm4t(u32* d, u32 a) {
    asm volatile("ldmatrix.sync.aligned.m8n8.x4.trans.shared.b16 {%0,%1,%2,%3}, [%4];"
                 : "=r"(d[0]), "=r"(d[1]), "=r"(d[2]), "=r"(d[3]) : "r"(a));
}
__device__ __forceinline__ void mma16816(float* c, const u32* a, const u32* b) {
    asm volatile("mma.sync.aligned.m16n8k16.row.col.f32.bf16.bf16.f32 "
                 "{%0,%1,%2,%3},{%4,%5,%6,%7},{%8,%9},{%0,%1,%2,%3};"
                 : "+f"(c[0]), "+f"(c[1]), "+f"(c[2]), "+f"(c[3])
                 : "r"(a[0]), "r"(a[1]), "r"(a[2]), "r"(a[3]), "r"(b[0]), "r"(b[1]));
}

// ---------------- weight split conversion: fp32 -> (hi,lo) bf16 planes ----------------
__global__ void split_kernel(const float* __restrict__ src, bf16* __restrict__ dst, long long n) {
    long long i = ((long long)blockIdx.x * 256 + threadIdx.x) * 4;
    float4 v = *reinterpret_cast<const float4*>(src + i);
    u32 h0, l0, h1, l1;
    split2(v.x, v.y, h0, l0);
    split2(v.z, v.w, h1, l1);
    *reinterpret_cast<uint2*>(dst + i)     = make_uint2(h0, h1);
    *reinterpret_cast<uint2*>(dst + n + i) = make_uint2(l0, l1);
}

// merged qkv weight split: dst[l][k][0:1024]=Wq, [1024:2048]=Wk, [2048:3072]=Wv
__global__ void split_qkv_kernel(const float* __restrict__ Wq, const float* __restrict__ Wk,
                                 const float* __restrict__ Wv, bf16* __restrict__ dst, long long n)
{
    long long i = ((long long)blockIdx.x * 256 + threadIdx.x) * 4;   // n = LQ*HQ*H3
    long long c  = i % H3;
    long long rl = i / H3;               // layer*1024 + k-row
    int seg = (int)(c >> 10);
    long long cc = c & 1023;
    const float* src = (seg == 0 ? Wq : seg == 1 ? Wk : Wv) + rl * 1024 + cc;
    float4 v = *reinterpret_cast<const float4*>(src);
    u32 h0, l0, h1, l1;
    split2(v.x, v.y, h0, l0);
    split2(v.z, v.w, h1, l1);
    *reinterpret_cast<uint2*>(dst + i)     = make_uint2(h0, h1);
    *reinterpret_cast<uint2*>(dst + n + i) = make_uint2(l0, l1);
}

__global__ void concat_bias_kernel(const float* __restrict__ bq, const float* __restrict__ bk,
                                   const float* __restrict__ bv, float* __restrict__ dst)
{
    int i = blockIdx.x * 256 + threadIdx.x;   // LQ*H3
    int c = i % H3, l = i / H3;
    int seg = c >> 10, cc = c & 1023;
    dst[i] = (seg == 0 ? bq : seg == 1 ? bk : bv)[l * 1024 + cc];
}

// ---------------- split-bf16 GEMM: mma.sync + 3-stage cp.async pipeline, 2 CTAs/SM ----------------
// C[M,N] = A[M,K] @ B ; A,B split bf16 (hi + lo planes, strides planeA/planeB)
// B gmem [K,N] (ldb = N-row stride) -> smem [K][N], ldmatrix.trans
// OUT: 0 fp32(+bias), 1 fp32+bias+residual R, 2 split(+bias), 3 split+bias+relu
template<int MT, int NT, int OUT>
__global__ __launch_bounds__(256, 2)
void mma_gemm(const bf16* __restrict__ A, long long planeA,
              const bf16* __restrict__ B, long long planeB,
              const float* __restrict__ bias, const float* __restrict__ R,
              void* __restrict__ Cv, long long planeC,
              int K, int lda, int ldb, int ldc)
{
    extern __shared__ char smem[];
    const u32 sb = (u32)__cvta_generic_to_shared(smem);

    constexpr int BK = 32;
    constexpr int AROW = 80;
    constexpr int A_BYTES = MT * AROW;
    constexpr int BROWB = NT * 2 + 16;
    constexpr int B_BYTES = BK * BROWB;
    constexpr int STAGE = 2 * A_BYTES + 2 * B_BYTES;
    constexpr int MTILES = MT / 32;
    constexpr int WMEXT  = MT / 2;
    constexpr int WN  = NT / 4;
    constexpr int N8  = WN / 8;
    constexpr int N16 = WN / 16;
    constexpr int C8N = NT / 8;
    constexpr int BUN = NT / 64;
    constexpr int AUN = MT / 64;

    const int tid = threadIdx.x, lane = tid & 31, wid = tid >> 5;
    const int wm = wid >> 2, wn = wid & 3;

    const int brow = blockIdx.x * MT;
    const int bcol = blockIdx.y * NT;
    const bf16* Ah = A;  const bf16* Al = Ah + planeA;
    const bf16* Bh = B;  const bf16* Bl = Bh + planeB;

    float acc[MTILES][N8][4];
    #pragma unroll
    for (int i = 0; i < MTILES; i++)
        #pragma unroll
        for (int j = 0; j < N8; j++)
            #pragma unroll
            for (int r = 0; r < 4; r++) acc[i][j][r] = 0.f;

#define ISSUE(stg_, kpos_) do {                                                     \
    const int kp_ = (kpos_);                                                        \
    const u32 base_ = sb + (u32)(stg_) * STAGE;                                     \
    _Pragma("unroll")                                                               \
    for (int i = 0; i < AUN; i++) {                                                 \
        int idx = tid + (i << 8); int r = idx >> 2; int c8 = idx & 3;               \
        long long g = (long long)(brow + r) * lda + kp_ + (c8 << 3);                \
        u32 off = (u32)r * AROW + (c8 << 4);                                        \
        cpa16(base_ + off, Ah + g);                                                 \
        cpa16(base_ + A_BYTES + off, Al + g);                                       \
    }                                                                               \
    _Pragma("unroll")                                                               \
    for (int i = 0; i < BUN; i++) {                                                 \
        int idx = tid + (i << 8);                                                   \
        int r = idx / C8N; int c8 = idx % C8N;                                      \
        long long g = (long long)(kp_ + r) * ldb + bcol + (c8 << 3);                \
        u32 off = (u32)r * BROWB + (c8 << 4);                                       \
        cpa16(base_ + 2 * A_BYTES + off, Bh + g);                                   \
        cpa16(base_ + 2 * A_BYTES + B_BYTES + off, Bl + g);                         \
    }                                                                               \
    asm volatile("cp.async.commit_group;");                                         \
} while (0)

    const int nk = K / BK;
    ISSUE(0, 0);
    ISSUE(1, BK);                              // nk >= 2 always (K >= 1024)

    for (int kt = 0; kt < nk; ++kt) {
        const int buf = kt % 3;
        if (kt + 2 < nk) asm volatile("cp.async.wait_group 1;");
        else             asm volatile("cp.async.wait_group 0;");
        __syncthreads();                       // stage ready + all warps done with overwritten buf
        if (kt + 2 < nk) ISSUE((kt + 2) % 3, (kt + 2) * BK);

        const u32 aHb = sb + (u32)buf * STAGE;
        const u32 aLb = aHb + A_BYTES;
        const u32 bHb = aLb + A_BYTES;
        const u32 bLb = bHb + B_BYTES;
        #pragma unroll
        for (int ks = 0; ks < 2; ++ks) {
            u32 bh[N8][2], bl[N8][2];
            #pragma unroll
            for (int n2 = 0; n2 < N16; ++n2) {
                u32 d0[4], d1[4];
                u32 off = (u32)(ks * 16 + (lane & 15)) * BROWB
                        + (u32)(wn * WN + ((lane >> 4) << 3) + n2 * 16) * 2;
                ldm4t(d0, bHb + off);
                ldm4t(d1, bLb + off);
                bh[2*n2][0] = d0[0]; bh[2*n2][1] = d0[1];
                bh[2*n2+1][0] = d0[2]; bh[2*n2+1][1] = d0[3];
                bl[2*n2][0] = d1[0]; bl[2*n2][1] = d1[1];
                bl[2*n2+1][0] = d1[2]; bl[2*n2+1][1] = d1[3];
            }
            #pragma unroll
            for (int mt = 0; mt < MTILES; ++mt) {
                u32 ah[4], al[4];
                u32 off = (u32)(wm * WMEXT + mt * 16 + (lane & 15)) * AROW
                        + (u32)(ks * 16 + ((lane >> 4) << 3)) * 2;
                ldm4(ah, aHb + off);
                ldm4(al, aLb + off);
                #pragma unroll
                for (int nt = 0; nt < N8; ++nt) {
                    mma16816(acc[mt][nt], ah, bh[nt]);
                    mma16816(acc[mt][nt], ah, bl[nt]);
                    mma16816(acc[mt][nt], al, bh[nt]);
                }
            }
        }
    }
#undef ISSUE

    // epilogue
    float* Cf = (float*)Cv;
    bf16*  Cb = (bf16*)Cv;
    #pragma unroll
    for (int mt = 0; mt < MTILES; ++mt) {
        #pragma unroll
        for (int nt = 0; nt < N8; ++nt) {
            int r0 = brow + wm * WMEXT + mt * 16 + (lane >> 2);
            int c0 = bcol + wn * WN + nt * 8 + ((lane & 3) << 1);
            float v0 = acc[mt][nt][0], v1 = acc[mt][nt][1];
            float v2 = acc[mt][nt][2], v3 = acc[mt][nt][3];
            if (bias) {
                float b0 = bias[c0], b1 = bias[c0 + 1];
                v0 += b0; v1 += b1; v2 += b0; v3 += b1;
            }
            if (OUT == 3) {
                v0 = fmaxf(v0, 0.f); v1 = fmaxf(v1, 0.f);
                v2 = fmaxf(v2, 0.f); v3 = fmaxf(v3, 0.f);
            }
            long long i0 = (long long)r0 * ldc + c0;
            long long i1 = (long long)(r0 + 8) * ldc + c0;
            if (OUT <= 1) {
                if (OUT == 1) {
                    v0 += R[i0]; v1 += R[i0 + 1];
                    v2 += R[i1]; v3 += R[i1 + 1];
                }
                *reinterpret_cast<float2*>(Cf + i0) = make_float2(v0, v1);
                *reinterpret_cast<float2*>(Cf + i1) = make_float2(v2, v3);
            } else {
                u32 h, l;
                split2(v0, v1, h, l);
                *reinterpret_cast<u32*>(Cb + i0) = h;
                *reinterpret_cast<u32*>(Cb + planeC + i0) = l;
                split2(v2, v3, h, l);
                *reinterpret_cast<u32*>(Cb + i1) = h;
                *reinterpret_cast<u32*>(Cb + planeC + i1) = l;
            }
        }
    }
}

// ---------------- fused flash attention (reads merged qkv buffer, stride H3) ----------------
// grid: (SQ/128, BQ*NHQ), 256 threads. Warp w owns Q rows [w*16, w*16+16).
__global__ __launch_bounds__(256, 2)
void flash_kernel(const bf16* __restrict__ QKV, bf16* __restrict__ Os,
                  long long PKV, long long PO)
{
    extern __shared__ char smem[];
    const u32 sb = (u32)__cvta_generic_to_shared(smem);
    constexpr int ROWB = 144;              // 64 bf16 = 128B + 16 pad
    constexpr int PL   = 64 * ROWB;        // one 64-row plane = 9216B
    constexpr int STAGE = 4 * PL;          // Kh,Kl,Vh,Vl = 36864B

    const int tid = threadIdx.x, lane = tid & 31, w = tid >> 5;
    const int bz = blockIdx.y;
    const int b = bz >> 4, hd = bz & 15;
    const int brow = blockIdx.x * 128;

    const bf16* Qh = QKV + ((long long)b * SQ + brow) * H3 + hd * 64;
    const bf16* Ql = Qh + PKV;
    const bf16* Kh = QKV + ((long long)b * SQ) * H3 + 1024 + hd * 64;
    const bf16* Kl = Kh + PKV;
    const bf16* Vh = QKV + ((long long)b * SQ) * H3 + 2048 + hd * 64;
    const bf16* Vl = Vh + PKV;

    // ---- stage Q through smem once, extract persistent fragments ----
    #pragma unroll
    for (int i = 0; i < 4; i++) {          // 128 rows x 8 chunks = 1024 / 256
        int idx = tid + (i << 8); int r = idx >> 3; int c8 = idx & 7;
        long long g = (long long)r * H3 + (c8 << 3);
        u32 off = (u32)r * ROWB + (c8 << 4);
        cpa16(sb + off, Qh + g);
        cpa16(sb + 2 * PL + off, Ql + g);
    }
    asm volatile("cp.async.commit_group;");
    asm volatile("cp.async.wait_group 0;");
    __syncthreads();
    u32 qh[4][4], ql[4][4];
    #pragma unroll
    for (int ks = 0; ks < 4; ++ks) {
        u32 off = (u32)(w * 16 + (lane & 15)) * ROWB + (u32)(ks * 16 + ((lane >> 4) << 3)) * 2;
        ldm4(qh[ks], sb + off);
        ldm4(ql[ks], sb + 2 * PL + off);
    }
    __syncthreads();                        // Q smem free

#define KVISSUE(buf_, j_) do {                                                  \
    const u32 base_ = sb + (u32)(buf_) * STAGE;                                 \
    _Pragma("unroll")                                                           \
    for (int i = 0; i < 2; i++) {          /* 64 rows x 8 chunks = 512 / 256 */ \
        int idx = tid + (i << 8); int r = idx >> 3; int c8 = idx & 7;           \
        long long g = (long long)((j_) * 64 + r) * H3 + (c8 << 3);              \
        u32 off = (u32)r * ROWB + (c8 << 4);                                    \
        cpa16(base_ + off,          Kh + g);                                    \
        cpa16(base_ + PL + off,     Kl + g);                                    \
        cpa16(base_ + 2 * PL + off, Vh + g);                                    \
        cpa16(base_ + 3 * PL + off, Vl + g);                                    \
    }                                                                           \
    asm volatile("cp.async.commit_group;");                                     \
} while (0)

    float oacc[8][4];
    #pragma unroll
    for (int i = 0; i < 8; i++)
        #pragma unroll
        for (int r = 0; r < 4; r++) oacc[i][r] = 0.f;
    float m0 = -1e30f, m1 = -1e30f, l0 = 0.f, l1 = 0.f;

    KVISSUE(0, 0);

    for (int j = 0; j < 16; ++j) {
        const int buf = j & 1;
        asm volatile("cp.async.wait_group 0;");
        __syncthreads();
        if (j + 1 < 16) KVISSUE(buf ^ 1, j + 1);

        const u32 kb = sb + (u32)buf * STAGE;

        // ---- S[16x64] = Q @ K^T (3-term split) ----
        float sacc[8][4];
        #pragma unroll
        for (int i = 0; i < 8; i++)
            #pragma unroll
            for (int r = 0; r < 4; r++) sacc[i][r] = 0.f;
        #pragma unroll
        for (int ks = 0; ks < 4; ++ks) {
            #pragma unroll
            for (int n2 = 0; n2 < 4; ++n2) {
                u32 d0[4], d1[4];
                u32 off = (u32)(n2 * 16 + (lane & 7) + ((lane >> 4) << 3)) * ROWB
                        + (u32)(ks * 16 + (((lane >> 3) & 1) << 3)) * 2;
                ldm4(d0, kb + off);            // K hi
                ldm4(d1, kb + PL + off);       // K lo
                u32 bh0[2] = {d0[0], d0[1]}, bh1[2] = {d0[2], d0[3]};
                u32 bl0[2] = {d1[0], d1[1]}, bl1[2] = {d1[2], d1[3]};
                mma16816(sacc[2*n2],   qh[ks], bh0);
                mma16816(sacc[2*n2],   qh[ks], bl0);
                mma16816(sacc[2*n2],   ql[ks], bh0);
                mma16816(sacc[2*n2+1], qh[ks], bh1);
                mma16816(sacc[2*n2+1], qh[ks], bl1);
                mma16816(sacc[2*n2+1], ql[ks], bh1);
            }
        }

        // ---- online softmax (rows in-warp: lanes {r*4..r*4+3} share a row) ----
        float mx0 = fmaxf(sacc[0][0], sacc[0][1]);
        float mx1 = fmaxf(sacc[0][2], sacc[0][3]);
        #pragma unroll
        for (int nt = 1; nt < 8; ++nt) {
            mx0 = fmaxf(mx0, fmaxf(sacc[nt][0], sacc[nt][1]));
            mx1 = fmaxf(mx1, fmaxf(sacc[nt][2], sacc[nt][3]));
        }
        mx0 = fmaxf(mx0, __shfl_xor_sync(0xffffffffu, mx0, 1));
        mx0 = fmaxf(mx0, __shfl_xor_sync(0xffffffffu, mx0, 2));
        mx1 = fmaxf(mx1, __shfl_xor_sync(0xffffffffu, mx1, 1));
        mx1 = fmaxf(mx1, __shfl_xor_sync(0xffffffffu, mx1, 2));
        float mn0 = fmaxf(m0, mx0), mn1 = fmaxf(m1, mx1);
        float c0 = __expf((m0 - mn0) * 0.125f);
        float c1 = __expf((m1 - mn1) * 0.125f);
        m0 = mn0; m1 = mn1;
        float s0 = 0.f, s1 = 0.f;
        #pragma unroll
        for (int nt = 0; nt < 8; ++nt) {
            sacc[nt][0] = __expf((sacc[nt][0] - m0) * 0.125f);
            sacc[nt][1] = __expf((sacc[nt][1] - m0) * 0.125f);
            sacc[nt][2] = __expf((sacc[nt][2] - m1) * 0.125f);
            sacc[nt][3] = __expf((sacc[nt][3] - m1) * 0.125f);
            s0 += sacc[nt][0] + sacc[nt][1];
            s1 += sacc[nt][2] + sacc[nt][3];
        }
        s0 += __shfl_xor_sync(0xffffffffu, s0, 1);
        s0 += __shfl_xor_sync(0xffffffffu, s0, 2);
        s1 += __shfl_xor_sync(0xffffffffu, s1, 1);
        s1 += __shfl_xor_sync(0xffffffffu, s1, 2);
        l0 = l0 * c0 + s0;
        l1 = l1 * c1 + s1;
        #pragma unroll
        for (int nt = 0; nt < 8; ++nt) {
            oacc[nt][0] *= c0; oacc[nt][1] *= c0;
            oacc[nt][2] *= c1; oacc[nt][3] *= c1;
        }

        // ---- O += P @ V (3-term split; P from sacc registers) ----
        #pragma unroll
        for (int ks = 0; ks < 4; ++ks) {
            u32 ph[4], pl[4];
            split2(sacc[2*ks][0],   sacc[2*ks][1],   ph[0], pl[0]);
            split2(sacc[2*ks][2],   sacc[2*ks][3],   ph[1], pl[1]);
            split2(sacc[2*ks+1][0], sacc[2*ks+1][1], ph[2], pl[2]);
            split2(sacc[2*ks+1][2], sacc[2*ks+1][3], ph[3], pl[3]);
            #pragma unroll
            for (int n2 = 0; n2 < 4; ++n2) {
                u32 d0[4], d1[4];
                u32 off = (u32)(ks * 16 + (lane & 15)) * ROWB
                        + (u32)(n2 * 16 + ((lane >> 4) << 3)) * 2;
                ldm4t(d0, kb + 2 * PL + off);   // V hi
                ldm4t(d1, kb + 3 * PL + off);   // V lo
                u32 bh0[2] = {d0[0], d0[1]}, bh1[2] = {d0[2], d0[3]};
                u32 bl0[2] = {d1[0], d1[1]}, bl1[2] = {d1[2], d1[3]};
                mma16816(oacc[2*n2],   ph, bh0);
                mma16816(oacc[2*n2],   ph, bl0);
                mma16816(oacc[2*n2],   pl, bh0);
                mma16816(oacc[2*n2+1], ph, bh1);
                mma16816(oacc[2*n2+1], ph, bl1);
                mma16816(oacc[2*n2+1], pl, bh1);
            }
        }
    }
#undef KVISSUE

    // ---- normalize + split-write O ----
    float inv0 = __frcp_rn(l0), inv1 = __frcp_rn(l1);
    bf16* Ob = Os + ((long long)b * SQ + brow) * HQ + hd * 64;
    #pragma unroll
    for (int nt = 0; nt < 8; ++nt) {
        int r0 = w * 16 + (lane >> 2);
        int c0 = nt * 8 + ((lane & 3) << 1);
        long long i0 = (long long)r0 * HQ + c0;
        long long i1 = (long long)(r0 + 8) * HQ + c0;
        u32 h, l;
        split2(oacc[nt][0] * inv0, oacc[nt][1] * inv0, h, l);
        *reinterpret_cast<u32*>(Ob + i0) = h;
        *reinterpret_cast<u32*>(Ob + PO + i0) = l;
        split2(oacc[nt][2] * inv1, oacc[nt][3] * inv1, h, l);
        *reinterpret_cast<u32*>(Ob + i1) = h;
        *reinterpret_cast<u32*>(Ob + PO + i1) = l;
    }
}

// ---------------- embedding + positional encoding (pe indexed by BATCH, per reference) ----------------
__global__ void embed_kernel(const int* __restrict__ x, const float* __restrict__ emb,
                             float* __restrict__ hf, bf16* __restrict__ hs, long long plane)
{
    int p   = blockIdx.x * blockDim.x + threadIdx.x;
    int e0  = p * 2;
    int j   = e0 & (HQ - 1);
    int row = e0 >> 10;
    int b   = row >> 10;
    int tok = x[row];
    const float c = -9.210340371976184f / (float)HQ;
    float div = __expf((float)(j & ~1) * c);
    float arg = (float)b * div;
    float s, co;
    __sincosf(arg, &s, &co);
    const float* ep = emb + (long long)tok * HQ + j;
    float v0 = ep[0] + s;
    float v1 = ep[1] + co;
    *reinterpret_cast<float2*>(hf + e0) = make_float2(v0, v1);
    u32 h, l;
    split2(v0, v1, h, l);
    *reinterpret_cast<u32*>(hs + e0) = h;
    *reinterpret_cast<u32*>(hs + plane + e0) = l;
}

// ---------------- LayerNorm over H=1024 : fp32 in, fp32 + split bf16 out ----------------
__global__ void ln_kernel(const float* __restrict__ X, const float* __restrict__ g,
                          const float* __restrict__ bta, float* __restrict__ Yf,
                          bf16* __restrict__ Ys, long long plane)
{
    __shared__ float ss[8], sq[8];
    const int t = threadIdx.x;   // 256
    const float* xr = X + (long long)blockIdx.x * HQ;
    float4 v = *reinterpret_cast<const float4*>(xr + 4 * t);
    float s = v.x + v.y + v.z + v.w;
    float q = v.x * v.x + v.y * v.y + v.z * v.z + v.w * v.w;
    #pragma unroll
    for (int o = 16; o; o >>= 1) {
        s += __shfl_xor_sync(0xffffffffu, s, o);
        q += __shfl_xor_sync(0xffffffffu, q, o);
    }
    if ((t & 31) == 0) { ss[t >> 5] = s; sq[t >> 5] = q; }
    __syncthreads();
    s = 0.f; q = 0.f;
    #pragma unroll
    for (int w = 0; w < 8; w++) { s += ss[w]; q += sq[w]; }
    float mean = s * (1.f / HQ);
    float var  = q * (1.f / HQ) - mean * mean;
    float inv  = rsqrtf(var + 1e-5f);
    float4 gg = *reinterpret_cast<const float4*>(g   + 4 * t);
    float4 bb = *reinterpret_cast<const float4*>(bta + 4 * t);
    float4 y;
    y.x = (v.x - mean) * inv * gg.x + bb.x;
    y.y = (v.y - mean) * inv * gg.y + bb.y;
    y.z = (v.z - mean) * inv * gg.z + bb.z;
    y.w = (v.w - mean) * inv * gg.w + bb.w;
    long long base = (long long)blockIdx.x * HQ + 4 * t;
    *reinterpret_cast<float4*>(Yf + base) = y;
    u32 h0, l0, h1, l1;
    split2(y.x, y.y, h0, l0); split2(y.z, y.w, h1, l1);
    *reinterpret_cast<uint2*>(Ys + base)         = make_uint2(h0, h1);
    *reinterpret_cast<uint2*>(Ys + plane + base) = make_uint2(l0, l1);
}

// ---------------- host launcher ----------------
extern "C" void kernel_launch(void* const* d_in, const int* in_sizes, int n_in,
                              void* d_out, int out_size)
{
    const int*   x    = (const int*)  d_in[0];
    const float* emb  = (const float*)d_in[1];
    const float* Wq   = (const float*)d_in[2];
    const float* bq   = (const float*)d_in[3];
    const float* Wk   = (const float*)d_in[4];
    const float* bk   = (const float*)d_in[5];
    const float* Wv   = (const float*)d_in[6];
    const float* bv   = (const float*)d_in[7];
    const float* Wo   = (const float*)d_in[8];
    const float* bo   = (const float*)d_in[9];
    const float* ln1g = (const float*)d_in[10];
    const float* ln1b = (const float*)d_in[11];
    const float* W1   = (const float*)d_in[12];
    const float* b1   = (const float*)d_in[13];
    const float* W2   = (const float*)d_in[14];
    const float* b2   = (const float*)d_in[15];
    const float* ln2g = (const float*)d_in[16];
    const float* ln2b = (const float*)d_in[17];
    const float* fcw  = (const float*)d_in[18];
    const float* fcb  = (const float*)d_in[19];
    float* out = (float*)d_out;

    float *h, *tt, *bqkv;
    bf16 *hs, *qkvs, *os, *fs, *wqkv, *wos, *w1s, *w2s, *fws;
    cudaGetSymbolAddress((void**)&h,    g_h);
    cudaGetSymbolAddress((void**)&tt,   g_t);
    cudaGetSymbolAddress((void**)&bqkv, g_bqkv);
    cudaGetSymbolAddress((void**)&hs,   g_hs);
    cudaGetSymbolAddress((void**)&qkvs, g_qkvs);
    cudaGetSymbolAddress((void**)&os,   g_os);
    cudaGetSymbolAddress((void**)&fs,   g_fs);
    cudaGetSymbolAddress((void**)&wqkv, g_wqkv);
    cudaGetSymbolAddress((void**)&wos,  g_wos);
    cudaGetSymbolAddress((void**)&w1s,  g_w1s);
    cudaGetSymbolAddress((void**)&w2s,  g_w2s);
    cudaGetSymbolAddress((void**)&fws,  g_fws);

    const int M = BQ * SQ;                               // 2048
    const long long PA  = (long long)BQ * SQ * HQ;
    const long long PA3 = (long long)BQ * SQ * H3;
    const long long PF  = (long long)BQ * SQ * FFQ;
    const long long PW  = (long long)LQ * HQ * HQ;
    const long long PW3 = (long long)LQ * HQ * H3;
    const long long PW1 = (long long)LQ * HQ * FFQ;
    const long long PFC = (long long)VQ * HQ;

    const int SM_T128 = 3 * (2 * 128 * 80 + 2 * 32 * (128 * 2 + 16));  // 113664 (3 stages)
    const int SM_FLASH = 2 * 4 * 64 * 144;                             // 73728

    cudaFuncSetAttribute(mma_gemm<128, 128, 0>, cudaFuncAttributeMaxDynamicSharedMemorySize, SM_T128);
    cudaFuncSetAttribute(mma_gemm<128, 128, 1>, cudaFuncAttributeMaxDynamicSharedMemorySize, SM_T128);
    cudaFuncSetAttribute(mma_gemm<128, 128, 2>, cudaFuncAttributeMaxDynamicSharedMemorySize, SM_T128);
    cudaFuncSetAttribute(mma_gemm<128, 128, 3>, cudaFuncAttributeMaxDynamicSharedMemorySize, SM_T128);
    cudaFuncSetAttribute(flash_kernel, cudaFuncAttributeMaxDynamicSharedMemorySize, SM_FLASH);

    // one-time weight conversions (part of the graph)
    split_qkv_kernel<<<(int)(PW3 / 1024), 256>>>(Wq, Wk, Wv, wqkv, PW3);
    concat_bias_kernel<<<(LQ * H3) / 256, 256>>>(bq, bk, bv, bqkv);
    split_kernel<<<(int)(PW  / 1024), 256>>>(Wo,  wos, PW);
    split_kernel<<<(int)(PW1 / 1024), 256>>>(W1,  w1s, PW1);
    split_kernel<<<(int)(PW1 / 1024), 256>>>(W2,  w2s, PW1);
    split_kernel<<<(int)(PFC / 1024), 256>>>(fcw, fws, PFC);

    embed_kernel<<<(M * HQ) / 512, 256>>>(x, emb, h, hs, PA);

    for (int l = 0; l < LQ; l++) {
        const bf16*  wqkvl = wqkv + (long long)l * HQ * H3;
        const float* bqkvl = bqkv + (long long)l * H3;
        const bf16* wol = wos + (long long)l * HQ * HQ;   const float* bol = bo + (long long)l * HQ;
        const bf16* w1l = w1s + (long long)l * HQ * FFQ;  const float* b1l = b1 + (long long)l * FFQ;
        const bf16* w2l = w2s + (long long)l * FFQ * HQ;  const float* b2l = b2 + (long long)l * HQ;

        // merged QKV: [2048,1024] @ [1024,3072] + bias -> split qkv buffer (384 CTAs)
        mma_gemm<128, 128, 2><<<dim3(M / 128, H3 / 128), 256, SM_T128>>>(
            hs, PA, wqkvl, PW3, bqkvl, nullptr, qkvs, PA3, HQ, HQ, H3, H3);

        // fused attention: scores + softmax + PV (reads merged qkv, stride H3)
        flash_kernel<<<dim3(SQ / 128, BQ * NHQ), 256, SM_FLASH>>>(qkvs, os, PA3, PA);

        // out projection + bias + residual(h) -> fp32 tt
        mma_gemm<128, 128, 1><<<dim3(M / 128, HQ / 128), 256, SM_T128>>>(
            os, PA, wol, PW, bol, h, tt, 0, HQ, HQ, HQ, HQ);
        ln_kernel<<<M, 256>>>(tt, ln1g + (long long)l * HQ, ln1b + (long long)l * HQ, h, hs, PA);

        // FFN
        mma_gemm<128, 128, 3><<<dim3(M / 128, FFQ / 128), 256, SM_T128>>>(
            hs, PA, w1l, PW1, b1l, nullptr, fs, PF, HQ, HQ, FFQ, FFQ);
        mma_gemm<128, 128, 1><<<dim3(M / 128, HQ / 128), 256, SM_T128>>>(
            fs, PF, w2l, PW1, b2l, h, tt, 0, FFQ, FFQ, HQ, HQ);
        ln_kernel<<<M, 256>>>(tt, ln2g + (long long)l * HQ, ln2b + (long long)l * HQ, h, hs, PA);
    }

    // final FC: [2048,1024] @ [1024,32000] + bias -> fp32 out
    mma_gemm<128, 128, 0><<<dim3(M / 128, VQ / 128), 256, SM_T128>>>(
        hs, PA, fws, PFC, fcb, nullptr, out, 0, HQ, HQ, VQ, VQ);
}

// round 16
// speedup vs baseline: 1.0001x; 1.0001x over previous
#include <cuda_runtime.h>
#include <cuda_bf16.h>
#include <math.h>

#define BQ 2
#define SQ 1024
#define HQ 1024
#define NHQ 16
#define HDQ 64
#define FFQ 4096
#define LQ 4
#define VQ 32000
#define H3 (3*HQ)

typedef unsigned int u32;
typedef unsigned long long u64;
typedef __nv_bfloat16 bf16;

// ---------------- scratch (static device globals; no allocation) ----------------
__device__ float g_h [BQ*SQ*HQ];
__device__ float g_t [BQ*SQ*HQ];
__device__ float g_bqkv[LQ*H3];                          // concatenated qkv bias
__device__ bf16 g_hs  [2LL*BQ*SQ*HQ];                    // split activations (hi plane, lo plane)
__device__ bf16 g_qkvs[2LL*BQ*SQ*H3];                    // merged qkv output (split)
__device__ bf16 g_os  [2LL*BQ*SQ*HQ];
__device__ bf16 g_fs  [2LL*BQ*SQ*FFQ];
__device__ bf16 g_wqkv[2LL*LQ*HQ*H3];                    // merged split qkv weights
__device__ bf16 g_wos [2LL*LQ*HQ*HQ];
__device__ bf16 g_w1s [2LL*LQ*HQ*FFQ];
__device__ bf16 g_w2s [2LL*LQ*FFQ*HQ];
__device__ bf16 g_fws [2LL*(long long)VQ*HQ];

// ---------------- helpers ----------------
__device__ __forceinline__ void split2(float x, float y, u32& hi, u32& lo) {
    __nv_bfloat162 h2 = __floats2bfloat162_rn(x, y);
    float2 bk = __bfloat1622float2(h2);
    __nv_bfloat162 l2 = __floats2bfloat162_rn(x - bk.x, y - bk.y);
    hi = *reinterpret_cast<u32*>(&h2);
    lo = *reinterpret_cast<u32*>(&l2);
}
__device__ __forceinline__ void cpa16(u32 saddr, const void* gaddr) {
    asm volatile("cp.async.cg.shared.global [%0], [%1], 16;" :: "r"(saddr), "l"(gaddr));
}
__device__ __forceinline__ void ldm4(u32* d, u32 a) {
    asm volatile("ldmatrix.sync.aligned.m8n8.x4.shared.b16 {%0,%1,%2,%3}, [%4];"
                 : "=r"(d[0]), "=r"(d[1]), "=r"(d[2]), "=r"(d[3]) : "r"(a));
}
__device__ __forceinline__ void ldm4t(u32* d, u32 a) {
    asm volatile("ldmatrix.sync.aligned.m8n8.x4.trans.shared.b16 {%0,%1,%2,%3}, [%4];"
                 : "=r"(d[0]), "=r"(d[1]), "=r"(d[2]), "=r"(d[3]) : "r"(a));
}
__device__ __forceinline__ void mma16816(float* c, const u32* a, const u32* b) {
    asm volatile("mma.sync.aligned.m16n8k16.row.col.f32.bf16.bf16.f32 "
                 "{%0,%1,%2,%3},{%4,%5,%6,%7},{%8,%9},{%0,%1,%2,%3};"
                 : "+f"(c[0]), "+f"(c[1]), "+f"(c[2]), "+f"(c[3])
                 : "r"(a[0]), "r"(a[1]), "r"(a[2]), "r"(a[3]), "r"(b[0]), "r"(b[1]));
}

// ---------------- weight split conversion: fp32 -> (hi,lo) bf16 planes ----------------
__global__ void split_kernel(const float* __restrict__ src, bf16* __restrict__ dst, long long n) {
    long long i = ((long long)blockIdx.x * 256 + threadIdx.x) * 4;
    float4 v = *reinterpret_cast<const float4*>(src + i);
    u32 h0, l0, h1, l1;
    split2(v.x, v.y, h0, l0);
    split2(v.z, v.w, h1, l1);
    *reinterpret_cast<uint2*>(dst + i)     = make_uint2(h0, h1);
    *reinterpret_cast<uint2*>(dst + n + i) = make_uint2(l0, l1);
}

// merged qkv weight split: dst[l][k][0:1024]=Wq, [1024:2048]=Wk, [2048:3072]=Wv
__global__ void split_qkv_kernel(const float* __restrict__ Wq, const float* __restrict__ Wk,
                                 const float* __restrict__ Wv, bf16* __restrict__ dst, long long n)
{
    long long i = ((long long)blockIdx.x * 256 + threadIdx.x) * 4;   // n = LQ*HQ*H3
    long long c  = i % H3;
    long long rl = i / H3;               // layer*1024 + k-row
    int seg = (int)(c >> 10);
    long long cc = c & 1023;
    const float* src = (seg == 0 ? Wq : seg == 1 ? Wk : Wv) + rl * 1024 + cc;
    float4 v = *reinterpret_cast<const float4*>(src);
    u32 h0, l0, h1, l1;
    split2(v.x, v.y, h0, l0);
    split2(v.z, v.w, h1, l1);
    *reinterpret_cast<uint2*>(dst + i)     = make_uint2(h0, h1);
    *reinterpret_cast<uint2*>(dst + n + i) = make_uint2(l0, l1);
}

__global__ void concat_bias_kernel(const float* __restrict__ bq, const float* __restrict__ bk,
                                   const float* __restrict__ bv, float* __restrict__ dst)
{
    int i = blockIdx.x * 256 + threadIdx.x;   // LQ*H3
    int c = i % H3, l = i / H3;
    int seg = c >> 10, cc = c & 1023;
    dst[i] = (seg == 0 ? bq : seg == 1 ? bk : bv)[l * 1024 + cc];
}

// ---------------- split-bf16 GEMM: mma.sync + 3-stage cp.async pipeline, 2 CTAs/SM ----------------
// C[M,N] = A[M,K] @ B ; A,B split bf16 (hi + lo planes, strides planeA/planeB)
// B gmem [K,N] (ldb = N-row stride) -> smem [K][N], ldmatrix.trans
// OUT: 0 fp32(+bias), 1 fp32+bias+residual R, 2 split(+bias), 3 split+bias+relu
template<int MT, int NT, int OUT>
__global__ __launch_bounds__(256, 2)
void mma_gemm(const bf16* __restrict__ A, long long planeA,
              const bf16* __restrict__ B, long long planeB,
              const float* __restrict__ bias, const float* __restrict__ R,
              void* __restrict__ Cv, long long planeC,
              int K, int lda, int ldb, int ldc)
{
    extern __shared__ char smem[];
    const u32 sb = (u32)__cvta_generic_to_shared(smem);

    constexpr int BK = 32;
    constexpr int AROW = 80;
    constexpr int A_BYTES = MT * AROW;
    constexpr int BROWB = NT * 2 + 16;
    constexpr int B_BYTES = BK * BROWB;
    constexpr int STAGE = 2 * A_BYTES + 2 * B_BYTES;
    constexpr int MTILES = MT / 32;
    constexpr int WMEXT  = MT / 2;
    constexpr int WN  = NT / 4;
    constexpr int N8  = WN / 8;
    constexpr int N16 = WN / 16;
    constexpr int C8N = NT / 8;
    constexpr int BUN = NT / 64;
    constexpr int AUN = MT / 64;

    const int tid = threadIdx.x, lane = tid & 31, wid = tid >> 5;
    const int wm = wid >> 2, wn = wid & 3;

    const int brow = blockIdx.x * MT;
    const int bcol = blockIdx.y * NT;
    const bf16* Ah = A;  const bf16* Al = Ah + planeA;
    const bf16* Bh = B;  const bf16* Bl = Bh + planeB;

    float acc[MTILES][N8][4];
    #pragma unroll
    for (int i = 0; i < MTILES; i++)
        #pragma unroll
        for (int j = 0; j < N8; j++)
            #pragma unroll
            for (int r = 0; r < 4; r++) acc[i][j][r] = 0.f;

#define ISSUE(stg_, kpos_) do {                                                     \
    const int kp_ = (kpos_);                                                        \
    const u32 base_ = sb + (u32)(stg_) * STAGE;                                     \
    _Pragma("unroll")                                                               \
    for (int i = 0; i < AUN; i++) {                                                 \
        int idx = tid + (i << 8); int r = idx >> 2; int c8 = idx & 3;               \
        long long g = (long long)(brow + r) * lda + kp_ + (c8 << 3);                \
        u32 off = (u32)r * AROW + (c8 << 4);                                        \
        cpa16(base_ + off, Ah + g);                                                 \
        cpa16(base_ + A_BYTES + off, Al + g);                                       \
    }                                                                               \
    _Pragma("unroll")                                                               \
    for (int i = 0; i < BUN; i++) {                                                 \
        int idx = tid + (i << 8);                                                   \
        int r = idx / C8N; int c8 = idx % C8N;                                      \
        long long g = (long long)(kp_ + r) * ldb + bcol + (c8 << 3);                \
        u32 off = (u32)r * BROWB + (c8 << 4);                                       \
        cpa16(base_ + 2 * A_BYTES + off, Bh + g);                                   \
        cpa16(base_ + 2 * A_BYTES + B_BYTES + off, Bl + g);                         \
    }                                                                               \
    asm volatile("cp.async.commit_group;");                                         \
} while (0)

    const int nk = K / BK;
    ISSUE(0, 0);
    ISSUE(1, BK);                              // nk >= 2 always (K >= 1024)

    for (int kt = 0; kt < nk; ++kt) {
        const int buf = kt % 3;
        if (kt + 2 < nk) asm volatile("cp.async.wait_group 1;");
        else             asm volatile("cp.async.wait_group 0;");
        __syncthreads();                       // stage ready + all warps done with overwritten buf
        if (kt + 2 < nk) ISSUE((kt + 2) % 3, (kt + 2) * BK);

        const u32 aHb = sb + (u32)buf * STAGE;
        const u32 aLb = aHb + A_BYTES;
        const u32 bHb = aLb + A_BYTES;
        const u32 bLb = bHb + B_BYTES;
        #pragma unroll
        for (int ks = 0; ks < 2; ++ks) {
            u32 bh[N8][2], bl[N8][2];
            #pragma unroll
            for (int n2 = 0; n2 < N16; ++n2) {
                u32 d0[4], d1[4];
                u32 off = (u32)(ks * 16 + (lane & 15)) * BROWB
                        + (u32)(wn * WN + ((lane >> 4) << 3) + n2 * 16) * 2;
                ldm4t(d0, bHb + off);
                ldm4t(d1, bLb + off);
                bh[2*n2][0] = d0[0]; bh[2*n2][1] = d0[1];
                bh[2*n2+1][0] = d0[2]; bh[2*n2+1][1] = d0[3];
                bl[2*n2][0] = d1[0]; bl[2*n2][1] = d1[1];
                bl[2*n2+1][0] = d1[2]; bl[2*n2+1][1] = d1[3];
            }
            #pragma unroll
            for (int mt = 0; mt < MTILES; ++mt) {
                u32 ah[4], al[4];
                u32 off = (u32)(wm * WMEXT + mt * 16 + (lane & 15)) * AROW
                        + (u32)(ks * 16 + ((lane >> 4) << 3)) * 2;
                ldm4(ah, aHb + off);
                ldm4(al, aLb + off);
                #pragma unroll
                for (int nt = 0; nt < N8; ++nt) {
                    mma16816(acc[mt][nt], ah, bh[nt]);
                    mma16816(acc[mt][nt], ah, bl[nt]);
                    mma16816(acc[mt][nt], al, bh[nt]);
                }
            }
        }
    }
#undef ISSUE

    // epilogue
    float* Cf = (float*)Cv;
    bf16*  Cb = (bf16*)Cv;
    #pragma unroll
    for (int mt = 0; mt < MTILES; ++mt) {
        #pragma unroll
        for (int nt = 0; nt < N8; ++nt) {
            int r0 = brow + wm * WMEXT + mt * 16 + (lane >> 2);
            int c0 = bcol + wn * WN + nt * 8 + ((lane & 3) << 1);
            float v0 = acc[mt][nt][0], v1 = acc[mt][nt][1];
            float v2 = acc[mt][nt][2], v3 = acc[mt][nt][3];
            if (bias) {
                float b0 = bias[c0], b1 = bias[c0 + 1];
                v0 += b0; v1 += b1; v2 += b0; v3 += b1;
            }
            if (OUT == 3) {
                v0 = fmaxf(v0, 0.f); v1 = fmaxf(v1, 0.f);
                v2 = fmaxf(v2, 0.f); v3 = fmaxf(v3, 0.f);
            }
            long long i0 = (long long)r0 * ldc + c0;
            long long i1 = (long long)(r0 + 8) * ldc + c0;
            if (OUT <= 1) {
                if (OUT == 1) {
                    v0 += R[i0]; v1 += R[i0 + 1];
                    v2 += R[i1]; v3 += R[i1 + 1];
                }
                *reinterpret_cast<float2*>(Cf + i0) = make_float2(v0, v1);
                *reinterpret_cast<float2*>(Cf + i1) = make_float2(v2, v3);
            } else {
                u32 h, l;
                split2(v0, v1, h, l);
                *reinterpret_cast<u32*>(Cb + i0) = h;
                *reinterpret_cast<u32*>(Cb + planeC + i0) = l;
                split2(v2, v3, h, l);
                *reinterpret_cast<u32*>(Cb + i1) = h;
                *reinterpret_cast<u32*>(Cb + planeC + i1) = l;
            }
        }
    }
}

// ---------------- fused flash attention (reads merged qkv buffer, stride H3) ----------------
// grid: (SQ/128, BQ*NHQ), 256 threads. Warp w owns Q rows [w*16, w*16+16).
__global__ __launch_bounds__(256, 2)
void flash_kernel(const bf16* __restrict__ QKV, bf16* __restrict__ Os,
                  long long PKV, long long PO)
{
    extern __shared__ char smem[];
    const u32 sb = (u32)__cvta_generic_to_shared(smem);
    constexpr int ROWB = 144;              // 64 bf16 = 128B + 16 pad
    constexpr int PL   = 64 * ROWB;        // one 64-row plane = 9216B
    constexpr int STAGE = 4 * PL;          // Kh,Kl,Vh,Vl = 36864B

    const int tid = threadIdx.x, lane = tid & 31, w = tid >> 5;
    const int bz = blockIdx.y;
    const int b = bz >> 4, hd = bz & 15;
    const int brow = blockIdx.x * 128;

    const bf16* Qh = QKV + ((long long)b * SQ + brow) * H3 + hd * 64;
    const bf16* Ql = Qh + PKV;
    const bf16* Kh = QKV + ((long long)b * SQ) * H3 + 1024 + hd * 64;
    const bf16* Kl = Kh + PKV;
    const bf16* Vh = QKV + ((long long)b * SQ) * H3 + 2048 + hd * 64;
    const bf16* Vl = Vh + PKV;

    // ---- stage Q through smem once, extract persistent fragments ----
    #pragma unroll
    for (int i = 0; i < 4; i++) {          // 128 rows x 8 chunks = 1024 / 256
        int idx = tid + (i << 8); int r = idx >> 3; int c8 = idx & 7;
        long long g = (long long)r * H3 + (c8 << 3);
        u32 off = (u32)r * ROWB + (c8 << 4);
        cpa16(sb + off, Qh + g);
        cpa16(sb + 2 * PL + off, Ql + g);
    }
    asm volatile("cp.async.commit_group;");
    asm volatile("cp.async.wait_group 0;");
    __syncthreads();
    u32 qh[4][4], ql[4][4];
    #pragma unroll
    for (int ks = 0; ks < 4; ++ks) {
        u32 off = (u32)(w * 16 + (lane & 15)) * ROWB + (u32)(ks * 16 + ((lane >> 4) << 3)) * 2;
        ldm4(qh[ks], sb + off);
        ldm4(ql[ks], sb + 2 * PL + off);
    }
    __syncthreads();                        // Q smem free

#define KVISSUE(buf_, j_) do {                                                  \
    const u32 base_ = sb + (u32)(buf_) * STAGE;                                 \
    _Pragma("unroll")                                                           \
    for (int i = 0; i < 2; i++) {          /* 64 rows x 8 chunks = 512 / 256 */ \
        int idx = tid + (i << 8); int r = idx >> 3; int c8 = idx & 7;           \
        long long g = (long long)((j_) * 64 + r) * H3 + (c8 << 3);              \
        u32 off = (u32)r * ROWB + (c8 << 4);                                    \
        cpa16(base_ + off,          Kh + g);                                    \
        cpa16(base_ + PL + off,     Kl + g);                                    \
        cpa16(base_ + 2 * PL + off, Vh + g);                                    \
        cpa16(base_ + 3 * PL + off, Vl + g);                                    \
    }                                                                           \
    asm volatile("cp.async.commit_group;");                                     \
} while (0)

    float oacc[8][4];
    #pragma unroll
    for (int i = 0; i < 8; i++)
        #pragma unroll
        for (int r = 0; r < 4; r++) oacc[i][r] = 0.f;
    float m0 = -1e30f, m1 = -1e30f, l0 = 0.f, l1 = 0.f;

    KVISSUE(0, 0);

    for (int j = 0; j < 16; ++j) {
        const int buf = j & 1;
        asm volatile("cp.async.wait_group 0;");
        __syncthreads();
        if (j + 1 < 16) KVISSUE(buf ^ 1, j + 1);

        const u32 kb = sb + (u32)buf * STAGE;

        // ---- S[16x64] = Q @ K^T (3-term split) ----
        float sacc[8][4];
        #pragma unroll
        for (int i = 0; i < 8; i++)
            #pragma unroll
            for (int r = 0; r < 4; r++) sacc[i][r] = 0.f;
        #pragma unroll
        for (int ks = 0; ks < 4; ++ks) {
            #pragma unroll
            for (int n2 = 0; n2 < 4; ++n2) {
                u32 d0[4], d1[4];
                u32 off = (u32)(n2 * 16 + (lane & 7) + ((lane >> 4) << 3)) * ROWB
                        + (u32)(ks * 16 + (((lane >> 3) & 1) << 3)) * 2;
                ldm4(d0, kb + off);            // K hi
                ldm4(d1, kb + PL + off);       // K lo
                u32 bh0[2] = {d0[0], d0[1]}, bh1[2] = {d0[2], d0[3]};
                u32 bl0[2] = {d1[0], d1[1]}, bl1[2] = {d1[2], d1[3]};
                mma16816(sacc[2*n2],   qh[ks], bh0);
                mma16816(sacc[2*n2],   qh[ks], bl0);
                mma16816(sacc[2*n2],   ql[ks], bh0);
                mma16816(sacc[2*n2+1], qh[ks], bh1);
                mma16816(sacc[2*n2+1], qh[ks], bl1);
                mma16816(sacc[2*n2+1], ql[ks], bh1);
            }
        }

        // ---- online softmax (rows in-warp: lanes {r*4..r*4+3} share a row) ----
        float mx0 = fmaxf(sacc[0][0], sacc[0][1]);
        float mx1 = fmaxf(sacc[0][2], sacc[0][3]);
        #pragma unroll
        for (int nt = 1; nt < 8; ++nt) {
            mx0 = fmaxf(mx0, fmaxf(sacc[nt][0], sacc[nt][1]));
            mx1 = fmaxf(mx1, fmaxf(sacc[nt][2], sacc[nt][3]));
        }
        mx0 = fmaxf(mx0, __shfl_xor_sync(0xffffffffu, mx0, 1));
        mx0 = fmaxf(mx0, __shfl_xor_sync(0xffffffffu, mx0, 2));
        mx1 = fmaxf(mx1, __shfl_xor_sync(0xffffffffu, mx1, 1));
        mx1 = fmaxf(mx1, __shfl_xor_sync(0xffffffffu, mx1, 2));
        float mn0 = fmaxf(m0, mx0), mn1 = fmaxf(m1, mx1);
        float c0 = __expf((m0 - mn0) * 0.125f);
        float c1 = __expf((m1 - mn1) * 0.125f);
        m0 = mn0; m1 = mn1;
        float s0 = 0.f, s1 = 0.f;
        #pragma unroll
        for (int nt = 0; nt < 8; ++nt) {
            sacc[nt][0] = __expf((sacc[nt][0] - m0) * 0.125f);
            sacc[nt][1] = __expf((sacc[nt][1] - m0) * 0.125f);
            sacc[nt][2] = __expf((sacc[nt][2] - m1) * 0.125f);
            sacc[nt][3] = __expf((sacc[nt][3] - m1) * 0.125f);
            s0 += sacc[nt][0] + sacc[nt][1];
            s1 += sacc[nt][2] + sacc[nt][3];
        }
        s0 += __shfl_xor_sync(0xffffffffu, s0, 1);
        s0 += __shfl_xor_sync(0xffffffffu, s0, 2);
        s1 += __shfl_xor_sync(0xffffffffu, s1, 1);
        s1 += __shfl_xor_sync(0xffffffffu, s1, 2);
        l0 = l0 * c0 + s0;
        l1 = l1 * c1 + s1;
        #pragma unroll
        for (int nt = 0; nt < 8; ++nt) {
            oacc[nt][0] *= c0; oacc[nt][1] *= c0;
            oacc[nt][2] *= c1; oacc[nt][3] *= c1;
        }

        // ---- O += P @ V (3-term split; P from sacc registers) ----
        #pragma unroll
        for (int ks = 0; ks < 4; ++ks) {
            u32 ph[4], pl[4];
            split2(sacc[2*ks][0],   sacc[2*ks][1],   ph[0], pl[0]);
            split2(sacc[2*ks][2],   sacc[2*ks][3],   ph[1], pl[1]);
            split2(sacc[2*ks+1][0], sacc[2*ks+1][1], ph[2], pl[2]);
            split2(sacc[2*ks+1][2], sacc[2*ks+1][3], ph[3], pl[3]);
            #pragma unroll
            for (int n2 = 0; n2 < 4; ++n2) {
                u32 d0[4], d1[4];
                u32 off = (u32)(ks * 16 + (lane & 15)) * ROWB
                        + (u32)(n2 * 16 + ((lane >> 4) << 3)) * 2;
                ldm4t(d0, kb + 2 * PL + off);   // V hi
                ldm4t(d1, kb + 3 * PL + off);   // V lo
                u32 bh0[2] = {d0[0], d0[1]}, bh1[2] = {d0[2], d0[3]};
                u32 bl0[2] = {d1[0], d1[1]}, bl1[2] = {d1[2], d1[3]};
                mma16816(oacc[2*n2],   ph, bh0);
                mma16816(oacc[2*n2],   ph, bl0);
                mma16816(oacc[2*n2],   pl, bh0);
                mma16816(oacc[2*n2+1], ph, bh1);
                mma16816(oacc[2*n2+1], ph, bl1);
                mma16816(oacc[2*n2+1], pl, bh1);
            }
        }
    }
#undef KVISSUE

    // ---- normalize + split-write O ----
    float inv0 = __frcp_rn(l0), inv1 = __frcp_rn(l1);
    bf16* Ob = Os + ((long long)b * SQ + brow) * HQ + hd * 64;
    #pragma unroll
    for (int nt = 0; nt < 8; ++nt) {
        int r0 = w * 16 + (lane >> 2);
        int c0 = nt * 8 + ((lane & 3) << 1);
        long long i0 = (long long)r0 * HQ + c0;
        long long i1 = (long long)(r0 + 8) * HQ + c0;
        u32 h, l;
        split2(oacc[nt][0] * inv0, oacc[nt][1] * inv0, h, l);
        *reinterpret_cast<u32*>(Ob + i0) = h;
        *reinterpret_cast<u32*>(Ob + PO + i0) = l;
        split2(oacc[nt][2] * inv1, oacc[nt][3] * inv1, h, l);
        *reinterpret_cast<u32*>(Ob + i1) = h;
        *reinterpret_cast<u32*>(Ob + PO + i1) = l;
    }
}

// ---------------- embedding + positional encoding (pe indexed by BATCH, per reference) ----------------
__global__ void embed_kernel(const int* __restrict__ x, const float* __restrict__ emb,
                             float* __restrict__ hf, bf16* __restrict__ hs, long long plane)
{
    int p   = blockIdx.x * blockDim.x + threadIdx.x;
    int e0  = p * 2;
    int j   = e0 & (HQ - 1);
    int row = e0 >> 10;
    int b   = row >> 10;
    int tok = x[row];
    const float c = -9.210340371976184f / (float)HQ;
    float div = __expf((float)(j & ~1) * c);
    float arg = (float)b * div;
    float s, co;
    __sincosf(arg, &s, &co);
    const float* ep = emb + (long long)tok * HQ + j;
    float v0 = ep[0] + s;
    float v1 = ep[1] + co;
    *reinterpret_cast<float2*>(hf + e0) = make_float2(v0, v1);
    u32 h, l;
    split2(v0, v1, h, l);
    *reinterpret_cast<u32*>(hs + e0) = h;
    *reinterpret_cast<u32*>(hs + plane + e0) = l;
}

// ---------------- LayerNorm over H=1024 : fp32 in, fp32 + split bf16 out ----------------
__global__ void ln_kernel(const float* __restrict__ X, const float* __restrict__ g,
                          const float* __restrict__ bta, float* __restrict__ Yf,
                          bf16* __restrict__ Ys, long long plane)
{
    __shared__ float ss[8], sq[8];
    const int t = threadIdx.x;   // 256
    const float* xr = X + (long long)blockIdx.x * HQ;
    float4 v = *reinterpret_cast<const float4*>(xr + 4 * t);
    float s = v.x + v.y + v.z + v.w;
    float q = v.x * v.x + v.y * v.y + v.z * v.z + v.w * v.w;
    #pragma unroll
    for (int o = 16; o; o >>= 1) {
        s += __shfl_xor_sync(0xffffffffu, s, o);
        q += __shfl_xor_sync(0xffffffffu, q, o);
    }
    if ((t & 31) == 0) { ss[t >> 5] = s; sq[t >> 5] = q; }
    __syncthreads();
    s = 0.f; q = 0.f;
    #pragma unroll
    for (int w = 0; w < 8; w++) { s += ss[w]; q += sq[w]; }
    float mean = s * (1.f / HQ);
    float var  = q * (1.f / HQ) - mean * mean;
    float inv  = rsqrtf(var + 1e-5f);
    float4 gg = *reinterpret_cast<const float4*>(g   + 4 * t);
    float4 bb = *reinterpret_cast<const float4*>(bta + 4 * t);
    float4 y;
    y.x = (v.x - mean) * inv * gg.x + bb.x;
    y.y = (v.y - mean) * inv * gg.y + bb.y;
    y.z = (v.z - mean) * inv * gg.z + bb.z;
    y.w = (v.w - mean) * inv * gg.w + bb.w;
    long long base = (long long)blockIdx.x * HQ + 4 * t;
    *reinterpret_cast<float4*>(Yf + base) = y;
    u32 h0, l0, h1, l1;
    split2(y.x, y.y, h0, l0); split2(y.z, y.w, h1, l1);
    *reinterpret_cast<uint2*>(Ys + base)         = make_uint2(h0, h1);
    *reinterpret_cast<uint2*>(Ys + plane + base) = make_uint2(l0, l1);
}

// ---------------- host launcher ----------------
extern "C" void kernel_launch(void* const* d_in, const int* in_sizes, int n_in,
                              void* d_out, int out_size)
{
    const int*   x    = (const int*)  d_in[0];
    const float* emb  = (const float*)d_in[1];
    const float* Wq   = (const float*)d_in[2];
    const float* bq   = (const float*)d_in[3];
    const float* Wk   = (const float*)d_in[4];
    const float* bk   = (const float*)d_in[5];
    const float* Wv   = (const float*)d_in[6];
    const float* bv   = (const float*)d_in[7];
    const float* Wo   = (const float*)d_in[8];
    const float* bo   = (const float*)d_in[9];
    const float* ln1g = (const float*)d_in[10];
    const float* ln1b = (const float*)d_in[11];
    const float* W1   = (const float*)d_in[12];
    const float* b1   = (const float*)d_in[13];
    const float* W2   = (const float*)d_in[14];
    const float* b2   = (const float*)d_in[15];
    const float* ln2g = (const float*)d_in[16];
    const float* ln2b = (const float*)d_in[17];
    const float* fcw  = (const float*)d_in[18];
    const float* fcb  = (const float*)d_in[19];
    float* out = (float*)d_out;

    float *h, *tt, *bqkv;
    bf16 *hs, *qkvs, *os, *fs, *wqkv, *wos, *w1s, *w2s, *fws;
    cudaGetSymbolAddress((void**)&h,    g_h);
    cudaGetSymbolAddress((void**)&tt,   g_t);
    cudaGetSymbolAddress((void**)&bqkv, g_bqkv);
    cudaGetSymbolAddress((void**)&hs,   g_hs);
    cudaGetSymbolAddress((void**)&qkvs, g_qkvs);
    cudaGetSymbolAddress((void**)&os,   g_os);
    cudaGetSymbolAddress((void**)&fs,   g_fs);
    cudaGetSymbolAddress((void**)&wqkv, g_wqkv);
    cudaGetSymbolAddress((void**)&wos,  g_wos);
    cudaGetSymbolAddress((void**)&w1s,  g_w1s);
    cudaGetSymbolAddress((void**)&w2s,  g_w2s);
    cudaGetSymbolAddress((void**)&fws,  g_fws);

    const int M = BQ * SQ;                               // 2048
    const long long PA  = (long long)BQ * SQ * HQ;
    const long long PA3 = (long long)BQ * SQ * H3;
    const long long PF  = (long long)BQ * SQ * FFQ;
    const long long PW  = (long long)LQ * HQ * HQ;
    const long long PW3 = (long long)LQ * HQ * H3;
    const long long PW1 = (long long)LQ * HQ * FFQ;
    const long long PFC = (long long)VQ * HQ;

    const int SM_T128 = 3 * (2 * 128 * 80 + 2 * 32 * (128 * 2 + 16));  // 113664 (3 stages)
    const int SM_FLASH = 2 * 4 * 64 * 144;                             // 73728

    cudaFuncSetAttribute(mma_gemm<128, 128, 0>, cudaFuncAttributeMaxDynamicSharedMemorySize, SM_T128);
    cudaFuncSetAttribute(mma_gemm<128, 128, 1>, cudaFuncAttributeMaxDynamicSharedMemorySize, SM_T128);
    cudaFuncSetAttribute(mma_gemm<128, 128, 2>, cudaFuncAttributeMaxDynamicSharedMemorySize, SM_T128);
    cudaFuncSetAttribute(mma_gemm<128, 128, 3>, cudaFuncAttributeMaxDynamicSharedMemorySize, SM_T128);
    cudaFuncSetAttribute(flash_kernel, cudaFuncAttributeMaxDynamicSharedMemorySize, SM_FLASH);

    // one-time weight conversions (part of the graph)
    split_qkv_kernel<<<(int)(PW3 / 1024), 256>>>(Wq, Wk, Wv, wqkv, PW3);
    concat_bias_kernel<<<(LQ * H3) / 256, 256>>>(bq, bk, bv, bqkv);
    split_kernel<<<(int)(PW  / 1024), 256>>>(Wo,  wos, PW);
    split_kernel<<<(int)(PW1 / 1024), 256>>>(W1,  w1s, PW1);
    split_kernel<<<(int)(PW1 / 1024), 256>>>(W2,  w2s, PW1);
    split_kernel<<<(int)(PFC / 1024), 256>>>(fcw, fws, PFC);

    embed_kernel<<<(M * HQ) / 512, 256>>>(x, emb, h, hs, PA);

    for (int l = 0; l < LQ; l++) {
        const bf16*  wqkvl = wqkv + (long long)l * HQ * H3;
        const float* bqkvl = bqkv + (long long)l * H3;
        const bf16* wol = wos + (long long)l * HQ * HQ;   const float* bol = bo + (long long)l * HQ;
        const bf16* w1l = w1s + (long long)l * HQ * FFQ;  const float* b1l = b1 + (long long)l * FFQ;
        const bf16* w2l = w2s + (long long)l * FFQ * HQ;  const float* b2l = b2 + (long long)l * HQ;

        // merged QKV: [2048,1024] @ [1024,3072] + bias -> split qkv buffer (384 CTAs)
        mma_gemm<128, 128, 2><<<dim3(M / 128, H3 / 128), 256, SM_T128>>>(
            hs, PA, wqkvl, PW3, bqkvl, nullptr, qkvs, PA3, HQ, HQ, H3, H3);

        // fused attention: scores + softmax + PV (reads merged qkv, stride H3)
        flash_kernel<<<dim3(SQ / 128, BQ * NHQ), 256, SM_FLASH>>>(qkvs, os, PA3, PA);

        // out projection + bias + residual(h) -> fp32 tt
        mma_gemm<128, 128, 1><<<dim3(M / 128, HQ / 128), 256, SM_T128>>>(
            os, PA, wol, PW, bol, h, tt, 0, HQ, HQ, HQ, HQ);
        ln_kernel<<<M, 256>>>(tt, ln1g + (long long)l * HQ, ln1b + (long long)l * HQ, h, hs, PA);

        // FFN
        mma_gemm<128, 128, 3><<<dim3(M / 128, FFQ / 128), 256, SM_T128>>>(
            hs, PA, w1l, PW1, b1l, nullptr, fs, PF, HQ, HQ, FFQ, FFQ);
        mma_gemm<128, 128, 1><<<dim3(M / 128, HQ / 128), 256, SM_T128>>>(
            fs, PF, w2l, PW1, b2l, h, tt, 0, FFQ, FFQ, HQ, HQ);
        ln_kernel<<<M, 256>>>(tt, ln2g + (long long)l * HQ, ln2b + (long long)l * HQ, h, hs, PA);
    }

    // final FC: [2048,1024] @ [1024,32000] + bias -> fp32 out
    mma_gemm<128, 128, 0><<<dim3(M / 128, VQ / 128), 256, SM_T128>>>(
        hs, PA, fws, PFC, fcb, nullptr, out, 0, HQ, HQ, VQ, VQ);
}

// round 17
// speedup vs baseline: 1.0001x; 1.0000x over previous
#include <cuda_runtime.h>
#include <cuda_bf16.h>
#include <math.h>

#define BQ 2
#define SQ 1024
#define HQ 1024
#define NHQ 16
#define HDQ 64
#define FFQ 4096
#define LQ 4
#define VQ 32000
#define H3 (3*HQ)

typedef unsigned int u32;
typedef unsigned long long u64;
typedef __nv_bfloat16 bf16;

// ---------------- scratch (static device globals; no allocation) ----------------
__device__ float g_h [BQ*SQ*HQ];
__device__ float g_t [BQ*SQ*HQ];
__device__ float g_bqkv[LQ*H3];                          // concatenated qkv bias
__device__ bf16 g_hs  [2LL*BQ*SQ*HQ];                    // split activations (hi plane, lo plane)
__device__ bf16 g_qkvs[2LL*BQ*SQ*H3];                    // merged qkv output (split)
__device__ bf16 g_os  [2LL*BQ*SQ*HQ];
__device__ bf16 g_fs  [2LL*BQ*SQ*FFQ];
__device__ bf16 g_wqkv[2LL*LQ*HQ*H3];                    // merged split qkv weights
__device__ bf16 g_wos [2LL*LQ*HQ*HQ];
__device__ bf16 g_w1s [2LL*LQ*HQ*FFQ];
__device__ bf16 g_w2s [2LL*LQ*FFQ*HQ];
__device__ bf16 g_fws [2LL*(long long)VQ*HQ];

// ---------------- helpers ----------------
__device__ __forceinline__ void split2(float x, float y, u32& hi, u32& lo) {
    __nv_bfloat162 h2 = __floats2bfloat162_rn(x, y);
    float2 bk = __bfloat1622float2(h2);
    __nv_bfloat162 l2 = __floats2bfloat162_rn(x - bk.x, y - bk.y);
    hi = *reinterpret_cast<u32*>(&h2);
    lo = *reinterpret_cast<u32*>(&l2);
}
__device__ __forceinline__ void cpa16(u32 saddr, const void* gaddr) {
    asm volatile("cp.async.cg.shared.global [%0], [%1], 16;" :: "r"(saddr), "l"(gaddr));
}
__device__ __forceinline__ void ldm4(u32* d, u32 a) {
    asm volatile("ldmatrix.sync.aligned.m8n8.x4.shared.b16 {%0,%1,%2,%3}, [%4];"
                 : "=r"(d[0]), "=r"(d[1]), "=r"(d[2]), "=r"(d[3]) : "r"(a));
}
__device__ __forceinline__ void ldm4t(u32* d, u32 a) {
    asm volatile("ldmatrix.sync.aligned.m8n8.x4.trans.shared.b16 {%0,%1,%2,%3}, [%4];"
                 : "=r"(d[0]), "=r"(d[1]), "=r"(d[2]), "=r"(d[3]) : "r"(a));
}
__device__ __forceinline__ void mma16816(float* c, const u32* a, const u32* b) {
    asm volatile("mma.sync.aligned.m16n8k16.row.col.f32.bf16.bf16.f32 "
                 "{%0,%1,%2,%3},{%4,%5,%6,%7},{%8,%9},{%0,%1,%2,%3};"
                 : "+f"(c[0]), "+f"(c[1]), "+f"(c[2]), "+f"(c[3])
                 : "r"(a[0]), "r"(a[1]), "r"(a[2]), "r"(a[3]), "r"(b[0]), "r"(b[1]));
}

// ---------------- weight split conversion: fp32 -> (hi,lo) bf16 planes ----------------
__global__ void split_kernel(const float* __restrict__ src, bf16* __restrict__ dst, long long n) {
    long long i = ((long long)blockIdx.x * 256 + threadIdx.x) * 4;
    float4 v = *reinterpret_cast<const float4*>(src + i);
    u32 h0, l0, h1, l1;
    split2(v.x, v.y, h0, l0);
    split2(v.z, v.w, h1, l1);
    *reinterpret_cast<uint2*>(dst + i)     = make_uint2(h0, h1);
    *reinterpret_cast<uint2*>(dst + n + i) = make_uint2(l0, l1);
}

// merged qkv weight split: dst[l][k][0:1024]=Wq, [1024:2048]=Wk, [2048:3072]=Wv
__global__ void split_qkv_kernel(const float* __restrict__ Wq, const float* __restrict__ Wk,
                                 const float* __restrict__ Wv, bf16* __restrict__ dst, long long n)
{
    long long i = ((long long)blockIdx.x * 256 + threadIdx.x) * 4;   // n = LQ*HQ*H3
    long long c  = i % H3;
    long long rl = i / H3;               // layer*1024 + k-row
    int seg = (int)(c >> 10);
    long long cc = c & 1023;
    const float* src = (seg == 0 ? Wq : seg == 1 ? Wk : Wv) + rl * 1024 + cc;
    float4 v = *reinterpret_cast<const float4*>(src);
    u32 h0, l0, h1, l1;
    split2(v.x, v.y, h0, l0);
    split2(v.z, v.w, h1, l1);
    *reinterpret_cast<uint2*>(dst + i)     = make_uint2(h0, h1);
    *reinterpret_cast<uint2*>(dst + n + i) = make_uint2(l0, l1);
}

__global__ void concat_bias_kernel(const float* __restrict__ bq, const float* __restrict__ bk,
                                   const float* __restrict__ bv, float* __restrict__ dst)
{
    int i = blockIdx.x * 256 + threadIdx.x;   // LQ*H3
    int c = i % H3, l = i / H3;
    int seg = c >> 10, cc = c & 1023;
    dst[i] = (seg == 0 ? bq : seg == 1 ? bk : bv)[l * 1024 + cc];
}

// ---------------- split-bf16 GEMM: mma.sync + 3-stage cp.async pipeline, 2 CTAs/SM ----------------
// C[M,N] = A[M,K] @ B ; A,B split bf16 (hi + lo planes, strides planeA/planeB)
// B gmem [K,N] (ldb = N-row stride) -> smem [K][N], ldmatrix.trans
// OUT: 0 fp32(+bias), 1 fp32+bias+residual R, 2 split(+bias), 3 split+bias+relu
template<int MT, int NT, int OUT>
__global__ __launch_bounds__(256, 2)
void mma_gemm(const bf16* __restrict__ A, long long planeA,
              const bf16* __restrict__ B, long long planeB,
              const float* __restrict__ bias, const float* __restrict__ R,
              void* __restrict__ Cv, long long planeC,
              int K, int lda, int ldb, int ldc)
{
    extern __shared__ char smem[];
    const u32 sb = (u32)__cvta_generic_to_shared(smem);

    constexpr int BK = 32;
    constexpr int AROW = 80;
    constexpr int A_BYTES = MT * AROW;
    constexpr int BROWB = NT * 2 + 16;
    constexpr int B_BYTES = BK * BROWB;
    constexpr int STAGE = 2 * A_BYTES + 2 * B_BYTES;
    constexpr int MTILES = MT / 32;
    constexpr int WMEXT  = MT / 2;
    constexpr int WN  = NT / 4;
    constexpr int N8  = WN / 8;
    constexpr int N16 = WN / 16;
    constexpr int C8N = NT / 8;
    constexpr int BUN = NT / 64;
    constexpr int AUN = MT / 64;

    const int tid = threadIdx.x, lane = tid & 31, wid = tid >> 5;
    const int wm = wid >> 2, wn = wid & 3;

    const int brow = blockIdx.x * MT;
    const int bcol = blockIdx.y * NT;
    const bf16* Ah = A;  const bf16* Al = Ah + planeA;
    const bf16* Bh = B;  const bf16* Bl = Bh + planeB;

    float acc[MTILES][N8][4];
    #pragma unroll
    for (int i = 0; i < MTILES; i++)
        #pragma unroll
        for (int j = 0; j < N8; j++)
            #pragma unroll
            for (int r = 0; r < 4; r++) acc[i][j][r] = 0.f;

#define ISSUE(stg_, kpos_) do {                                                     \
    const int kp_ = (kpos_);                                                        \
    const u32 base_ = sb + (u32)(stg_) * STAGE;                                     \
    _Pragma("unroll")                                                               \
    for (int i = 0; i < AUN; i++) {                                                 \
        int idx = tid + (i << 8); int r = idx >> 2; int c8 = idx & 3;               \
        long long g = (long long)(brow + r) * lda + kp_ + (c8 << 3);                \
        u32 off = (u32)r * AROW + (c8 << 4);                                        \
        cpa16(base_ + off, Ah + g);                                                 \
        cpa16(base_ + A_BYTES + off, Al + g);                                       \
    }                                                                               \
    _Pragma("unroll")                                                               \
    for (int i = 0; i < BUN; i++) {                                                 \
        int idx = tid + (i << 8);                                                   \
        int r = idx / C8N; int c8 = idx % C8N;                                      \
        long long g = (long long)(kp_ + r) * ldb + bcol + (c8 << 3);                \
        u32 off = (u32)r * BROWB + (c8 << 4);                                       \
        cpa16(base_ + 2 * A_BYTES + off, Bh + g);                                   \
        cpa16(base_ + 2 * A_BYTES + B_BYTES + off, Bl + g);                         \
    }                                                                               \
    asm volatile("cp.async.commit_group;");                                         \
} while (0)

    const int nk = K / BK;
    ISSUE(0, 0);
    ISSUE(1, BK);                              // nk >= 2 always (K >= 1024)

    for (int kt = 0; kt < nk; ++kt) {
        const int buf = kt % 3;
        if (kt + 2 < nk) asm volatile("cp.async.wait_group 1;");
        else             asm volatile("cp.async.wait_group 0;");
        __syncthreads();                       // stage ready + all warps done with overwritten buf
        if (kt + 2 < nk) ISSUE((kt + 2) % 3, (kt + 2) * BK);

        const u32 aHb = sb + (u32)buf * STAGE;
        const u32 aLb = aHb + A_BYTES;
        const u32 bHb = aLb + A_BYTES;
        const u32 bLb = bHb + B_BYTES;
        #pragma unroll
        for (int ks = 0; ks < 2; ++ks) {
            u32 bh[N8][2], bl[N8][2];
            #pragma unroll
            for (int n2 = 0; n2 < N16; ++n2) {
                u32 d0[4], d1[4];
                u32 off = (u32)(ks * 16 + (lane & 15)) * BROWB
                        + (u32)(wn * WN + ((lane >> 4) << 3) + n2 * 16) * 2;
                ldm4t(d0, bHb + off);
                ldm4t(d1, bLb + off);
                bh[2*n2][0] = d0[0]; bh[2*n2][1] = d0[1];
                bh[2*n2+1][0] = d0[2]; bh[2*n2+1][1] = d0[3];
                bl[2*n2][0] = d1[0]; bl[2*n2][1] = d1[1];
                bl[2*n2+1][0] = d1[2]; bl[2*n2+1][1] = d1[3];
            }
            #pragma unroll
            for (int mt = 0; mt < MTILES; ++mt) {
                u32 ah[4], al[4];
                u32 off = (u32)(wm * WMEXT + mt * 16 + (lane & 15)) * AROW
                        + (u32)(ks * 16 + ((lane >> 4) << 3)) * 2;
                ldm4(ah, aHb + off);
                ldm4(al, aLb + off);
                #pragma unroll
                for (int nt = 0; nt < N8; ++nt) {
                    mma16816(acc[mt][nt], ah, bh[nt]);
                    mma16816(acc[mt][nt], ah, bl[nt]);
                    mma16816(acc[mt][nt], al, bh[nt]);
                }
            }
        }
    }
#undef ISSUE

    // epilogue
    float* Cf = (float*)Cv;
    bf16*  Cb = (bf16*)Cv;
    #pragma unroll
    for (int mt = 0; mt < MTILES; ++mt) {
        #pragma unroll
        for (int nt = 0; nt < N8; ++nt) {
            int r0 = brow + wm * WMEXT + mt * 16 + (lane >> 2);
            int c0 = bcol + wn * WN + nt * 8 + ((lane & 3) << 1);
            float v0 = acc[mt][nt][0], v1 = acc[mt][nt][1];
            float v2 = acc[mt][nt][2], v3 = acc[mt][nt][3];
            if (bias) {
                float b0 = bias[c0], b1 = bias[c0 + 1];
                v0 += b0; v1 += b1; v2 += b0; v3 += b1;
            }
            if (OUT == 3) {
                v0 = fmaxf(v0, 0.f); v1 = fmaxf(v1, 0.f);
                v2 = fmaxf(v2, 0.f); v3 = fmaxf(v3, 0.f);
            }
            long long i0 = (long long)r0 * ldc + c0;
            long long i1 = (long long)(r0 + 8) * ldc + c0;
            if (OUT <= 1) {
                if (OUT == 1) {
                    v0 += R[i0]; v1 += R[i0 + 1];
                    v2 += R[i1]; v3 += R[i1 + 1];
                }
                *reinterpret_cast<float2*>(Cf + i0) = make_float2(v0, v1);
                *reinterpret_cast<float2*>(Cf + i1) = make_float2(v2, v3);
            } else {
                u32 h, l;
                split2(v0, v1, h, l);
                *reinterpret_cast<u32*>(Cb + i0) = h;
                *reinterpret_cast<u32*>(Cb + planeC + i0) = l;
                split2(v2, v3, h, l);
                *reinterpret_cast<u32*>(Cb + i1) = h;
                *reinterpret_cast<u32*>(Cb + planeC + i1) = l;
            }
        }
    }
}

// ---------------- fused flash attention (reads merged qkv buffer, stride H3) ----------------
// grid: (SQ/128, BQ*NHQ), 256 threads. Warp w owns Q rows [w*16, w*16+16).
__global__ __launch_bounds__(256, 2)
void flash_kernel(const bf16* __restrict__ QKV, bf16* __restrict__ Os,
                  long long PKV, long long PO)
{
    extern __shared__ char smem[];
    const u32 sb = (u32)__cvta_generic_to_shared(smem);
    constexpr int ROWB = 144;              // 64 bf16 = 128B + 16 pad
    constexpr int PL   = 64 * ROWB;        // one 64-row plane = 9216B
    constexpr int STAGE = 4 * PL;          // Kh,Kl,Vh,Vl = 36864B

    const int tid = threadIdx.x, lane = tid & 31, w = tid >> 5;
    const int bz = blockIdx.y;
    const int b = bz >> 4, hd = bz & 15;
    const int brow = blockIdx.x * 128;

    const bf16* Qh = QKV + ((long long)b * SQ + brow) * H3 + hd * 64;
    const bf16* Ql = Qh + PKV;
    const bf16* Kh = QKV + ((long long)b * SQ) * H3 + 1024 + hd * 64;
    const bf16* Kl = Kh + PKV;
    const bf16* Vh = QKV + ((long long)b * SQ) * H3 + 2048 + hd * 64;
    const bf16* Vl = Vh + PKV;

    // ---- stage Q through smem once, extract persistent fragments ----
    #pragma unroll
    for (int i = 0; i < 4; i++) {          // 128 rows x 8 chunks = 1024 / 256
        int idx = tid + (i << 8); int r = idx >> 3; int c8 = idx & 7;
        long long g = (long long)r * H3 + (c8 << 3);
        u32 off = (u32)r * ROWB + (c8 << 4);
        cpa16(sb + off, Qh + g);
        cpa16(sb + 2 * PL + off, Ql + g);
    }
    asm volatile("cp.async.commit_group;");
    asm volatile("cp.async.wait_group 0;");
    __syncthreads();
    u32 qh[4][4], ql[4][4];
    #pragma unroll
    for (int ks = 0; ks < 4; ++ks) {
        u32 off = (u32)(w * 16 + (lane & 15)) * ROWB + (u32)(ks * 16 + ((lane >> 4) << 3)) * 2;
        ldm4(qh[ks], sb + off);
        ldm4(ql[ks], sb + 2 * PL + off);
    }
    __syncthreads();                        // Q smem free

#define KVISSUE(buf_, j_) do {                                                  \
    const u32 base_ = sb + (u32)(buf_) * STAGE;                                 \
    _Pragma("unroll")                                                           \
    for (int i = 0; i < 2; i++) {          /* 64 rows x 8 chunks = 512 / 256 */ \
        int idx = tid + (i << 8); int r = idx >> 3; int c8 = idx & 7;           \
        long long g = (long long)((j_) * 64 + r) * H3 + (c8 << 3);              \
        u32 off = (u32)r * ROWB + (c8 << 4);                                    \
        cpa16(base_ + off,          Kh + g);                                    \
        cpa16(base_ + PL + off,     Kl + g);                                    \
        cpa16(base_ + 2 * PL + off, Vh + g);                                    \
        cpa16(base_ + 3 * PL + off, Vl + g);                                    \
    }                                                                           \
    asm volatile("cp.async.commit_group;");                                     \
} while (0)

    float oacc[8][4];
    #pragma unroll
    for (int i = 0; i < 8; i++)
        #pragma unroll
        for (int r = 0; r < 4; r++) oacc[i][r] = 0.f;
    float m0 = -1e30f, m1 = -1e30f, l0 = 0.f, l1 = 0.f;

    KVISSUE(0, 0);

    for (int j = 0; j < 16; ++j) {
        const int buf = j & 1;
        asm volatile("cp.async.wait_group 0;");
        __syncthreads();
        if (j + 1 < 16) KVISSUE(buf ^ 1, j + 1);

        const u32 kb = sb + (u32)buf * STAGE;

        // ---- S[16x64] = Q @ K^T (3-term split) ----
        float sacc[8][4];
        #pragma unroll
        for (int i = 0; i < 8; i++)
            #pragma unroll
            for (int r = 0; r < 4; r++) sacc[i][r] = 0.f;
        #pragma unroll
        for (int ks = 0; ks < 4; ++ks) {
            #pragma unroll
            for (int n2 = 0; n2 < 4; ++n2) {
                u32 d0[4], d1[4];
                u32 off = (u32)(n2 * 16 + (lane & 7) + ((lane >> 4) << 3)) * ROWB
                        + (u32)(ks * 16 + (((lane >> 3) & 1) << 3)) * 2;
                ldm4(d0, kb + off);            // K hi
                ldm4(d1, kb + PL + off);       // K lo
                u32 bh0[2] = {d0[0], d0[1]}, bh1[2] = {d0[2], d0[3]};
                u32 bl0[2] = {d1[0], d1[1]}, bl1[2] = {d1[2], d1[3]};
                mma16816(sacc[2*n2],   qh[ks], bh0);
                mma16816(sacc[2*n2],   qh[ks], bl0);
                mma16816(sacc[2*n2],   ql[ks], bh0);
                mma16816(sacc[2*n2+1], qh[ks], bh1);
                mma16816(sacc[2*n2+1], qh[ks], bl1);
                mma16816(sacc[2*n2+1], ql[ks], bh1);
            }
        }

        // ---- online softmax (rows in-warp: lanes {r*4..r*4+3} share a row) ----
        float mx0 = fmaxf(sacc[0][0], sacc[0][1]);
        float mx1 = fmaxf(sacc[0][2], sacc[0][3]);
        #pragma unroll
        for (int nt = 1; nt < 8; ++nt) {
            mx0 = fmaxf(mx0, fmaxf(sacc[nt][0], sacc[nt][1]));
            mx1 = fmaxf(mx1, fmaxf(sacc[nt][2], sacc[nt][3]));
        }
        mx0 = fmaxf(mx0, __shfl_xor_sync(0xffffffffu, mx0, 1));
        mx0 = fmaxf(mx0, __shfl_xor_sync(0xffffffffu, mx0, 2));
        mx1 = fmaxf(mx1, __shfl_xor_sync(0xffffffffu, mx1, 1));
        mx1 = fmaxf(mx1, __shfl_xor_sync(0xffffffffu, mx1, 2));
        float mn0 = fmaxf(m0, mx0), mn1 = fmaxf(m1, mx1);
        float c0 = __expf((m0 - mn0) * 0.125f);
        float c1 = __expf((m1 - mn1) * 0.125f);
        m0 = mn0; m1 = mn1;
        float s0 = 0.f, s1 = 0.f;
        #pragma unroll
        for (int nt = 0; nt < 8; ++nt) {
            sacc[nt][0] = __expf((sacc[nt][0] - m0) * 0.125f);
            sacc[nt][1] = __expf((sacc[nt][1] - m0) * 0.125f);
            sacc[nt][2] = __expf((sacc[nt][2] - m1) * 0.125f);
            sacc[nt][3] = __expf((sacc[nt][3] - m1) * 0.125f);
            s0 += sacc[nt][0] + sacc[nt][1];
            s1 += sacc[nt][2] + sacc[nt][3];
        }
        s0 += __shfl_xor_sync(0xffffffffu, s0, 1);
        s0 += __shfl_xor_sync(0xffffffffu, s0, 2);
        s1 += __shfl_xor_sync(0xffffffffu, s1, 1);
        s1 += __shfl_xor_sync(0xffffffffu, s1, 2);
        l0 = l0 * c0 + s0;
        l1 = l1 * c1 + s1;
        #pragma unroll
        for (int nt = 0; nt < 8; ++nt) {
            oacc[nt][0] *= c0; oacc[nt][1] *= c0;
            oacc[nt][2] *= c1; oacc[nt][3] *= c1;
        }

        // ---- O += P @ V (3-term split; P from sacc registers) ----
        #pragma unroll
        for (int ks = 0; ks < 4; ++ks) {
            u32 ph[4], pl[4];
            split2(sacc[2*ks][0],   sacc[2*ks][1],   ph[0], pl[0]);
            split2(sacc[2*ks][2],   sacc[2*ks][3],   ph[1], pl[1]);
            split2(sacc[2*ks+1][0], sacc[2*ks+1][1], ph[2], pl[2]);
            split2(sacc[2*ks+1][2], sacc[2*ks+1][3], ph[3], pl[3]);
            #pragma unroll
            for (int n2 = 0; n2 < 4; ++n2) {
                u32 d0[4], d1[4];
                u32 off = (u32)(ks * 16 + (lane & 15)) * ROWB
                        + (u32)(n2 * 16 + ((lane >> 4) << 3)) * 2;
                ldm4t(d0, kb + 2 * PL + off);   // V hi
                ldm4t(d1, kb + 3 * PL + off);   // V lo
                u32 bh0[2] = {d0[0], d0[1]}, bh1[2] = {d0[2], d0[3]};
                u32 bl0[2] = {d1[0], d1[1]}, bl1[2] = {d1[2], d1[3]};
                mma16816(oacc[2*n2],   ph, bh0);
                mma16816(oacc[2*n2],   ph, bl0);
                mma16816(oacc[2*n2],   pl, bh0);
                mma16816(oacc[2*n2+1], ph, bh1);
                mma16816(oacc[2*n2+1], ph, bl1);
                mma16816(oacc[2*n2+1], pl, bh1);
            }
        }
    }
#undef KVISSUE

    // ---- normalize + split-write O ----
    float inv0 = __frcp_rn(l0), inv1 = __frcp_rn(l1);
    bf16* Ob = Os + ((long long)b * SQ + brow) * HQ + hd * 64;
    #pragma unroll
    for (int nt = 0; nt < 8; ++nt) {
        int r0 = w * 16 + (lane >> 2);
        int c0 = nt * 8 + ((lane & 3) << 1);
        long long i0 = (long long)r0 * HQ + c0;
        long long i1 = (long long)(r0 + 8) * HQ + c0;
        u32 h, l;
        split2(oacc[nt][0] * inv0, oacc[nt][1] * inv0, h, l);
        *reinterpret_cast<u32*>(Ob + i0) = h;
        *reinterpret_cast<u32*>(Ob + PO + i0) = l;
        split2(oacc[nt][2] * inv1, oacc[nt][3] * inv1, h, l);
        *reinterpret_cast<u32*>(Ob + i1) = h;
        *reinterpret_cast<u32*>(Ob + PO + i1) = l;
    }
}

// ---------------- embedding + positional encoding (pe indexed by BATCH, per reference) ----------------
__global__ void embed_kernel(const int* __restrict__ x, const float* __restrict__ emb,
                             float* __restrict__ hf, bf16* __restrict__ hs, long long plane)
{
    int p   = blockIdx.x * blockDim.x + threadIdx.x;
    int e0  = p * 2;
    int j   = e0 & (HQ - 1);
    int row = e0 >> 10;
    int b   = row >> 10;
    int tok = x[row];
    const float c = -9.210340371976184f / (float)HQ;
    float div = __expf((float)(j & ~1) * c);
    float arg = (float)b * div;
    float s, co;
    __sincosf(arg, &s, &co);
    const float* ep = emb + (long long)tok * HQ + j;
    float v0 = ep[0] + s;
    float v1 = ep[1] + co;
    *reinterpret_cast<float2*>(hf + e0) = make_float2(v0, v1);
    u32 h, l;
    split2(v0, v1, h, l);
    *reinterpret_cast<u32*>(hs + e0) = h;
    *reinterpret_cast<u32*>(hs + plane + e0) = l;
}

// ---------------- LayerNorm over H=1024 : fp32 in, fp32 + split bf16 out ----------------
__global__ void ln_kernel(const float* __restrict__ X, const float* __restrict__ g,
                          const float* __restrict__ bta, float* __restrict__ Yf,
                          bf16* __restrict__ Ys, long long plane)
{
    __shared__ float ss[8], sq[8];
    const int t = threadIdx.x;   // 256
    const float* xr = X + (long long)blockIdx.x * HQ;
    float4 v = *reinterpret_cast<const float4*>(xr + 4 * t);
    float s = v.x + v.y + v.z + v.w;
    float q = v.x * v.x + v.y * v.y + v.z * v.z + v.w * v.w;
    #pragma unroll
    for (int o = 16; o; o >>= 1) {
        s += __shfl_xor_sync(0xffffffffu, s, o);
        q += __shfl_xor_sync(0xffffffffu, q, o);
    }
    if ((t & 31) == 0) { ss[t >> 5] = s; sq[t >> 5] = q; }
    __syncthreads();
    s = 0.f; q = 0.f;
    #pragma unroll
    for (int w = 0; w < 8; w++) { s += ss[w]; q += sq[w]; }
    float mean = s * (1.f / HQ);
    float var  = q * (1.f / HQ) - mean * mean;
    float inv  = rsqrtf(var + 1e-5f);
    float4 gg = *reinterpret_cast<const float4*>(g   + 4 * t);
    float4 bb = *reinterpret_cast<const float4*>(bta + 4 * t);
    float4 y;
    y.x = (v.x - mean) * inv * gg.x + bb.x;
    y.y = (v.y - mean) * inv * gg.y + bb.y;
    y.z = (v.z - mean) * inv * gg.z + bb.z;
    y.w = (v.w - mean) * inv * gg.w + bb.w;
    long long base = (long long)blockIdx.x * HQ + 4 * t;
    *reinterpret_cast<float4*>(Yf + base) = y;
    u32 h0, l0, h1, l1;
    split2(y.x, y.y, h0, l0); split2(y.z, y.w, h1, l1);
    *reinterpret_cast<uint2*>(Ys + base)         = make_uint2(h0, h1);
    *reinterpret_cast<uint2*>(Ys + plane + base) = make_uint2(l0, l1);
}

// ---------------- host launcher ----------------
extern "C" void kernel_launch(void* const* d_in, const int* in_sizes, int n_in,
                              void* d_out, int out_size)
{
    const int*   x    = (const int*)  d_in[0];
    const float* emb  = (const float*)d_in[1];
    const float* Wq   = (const float*)d_in[2];
    const float* bq   = (const float*)d_in[3];
    const float* Wk   = (const float*)d_in[4];
    const float* bk   = (const float*)d_in[5];
    const float* Wv   = (const float*)d_in[6];
    const float* bv   = (const float*)d_in[7];
    const float* Wo   = (const float*)d_in[8];
    const float* bo   = (const float*)d_in[9];
    const float* ln1g = (const float*)d_in[10];
    const float* ln1b = (const float*)d_in[11];
    const float* W1   = (const float*)d_in[12];
    const float* b1   = (const float*)d_in[13];
    const float* W2   = (const float*)d_in[14];
    const float* b2   = (const float*)d_in[15];
    const float* ln2g = (const float*)d_in[16];
    const float* ln2b = (const float*)d_in[17];
    const float* fcw  = (const float*)d_in[18];
    const float* fcb  = (const float*)d_in[19];
    float* out = (float*)d_out;

    float *h, *tt, *bqkv;
    bf16 *hs, *qkvs, *os, *fs, *wqkv, *wos, *w1s, *w2s, *fws;
    cudaGetSymbolAddress((void**)&h,    g_h);
    cudaGetSymbolAddress((void**)&tt,   g_t);
    cudaGetSymbolAddress((void**)&bqkv, g_bqkv);
    cudaGetSymbolAddress((void**)&hs,   g_hs);
    cudaGetSymbolAddress((void**)&qkvs, g_qkvs);
    cudaGetSymbolAddress((void**)&os,   g_os);
    cudaGetSymbolAddress((void**)&fs,   g_fs);
    cudaGetSymbolAddress((void**)&wqkv, g_wqkv);
    cudaGetSymbolAddress((void**)&wos,  g_wos);
    cudaGetSymbolAddress((void**)&w1s,  g_w1s);
    cudaGetSymbolAddress((void**)&w2s,  g_w2s);
    cudaGetSymbolAddress((void**)&fws,  g_fws);

    const int M = BQ * SQ;                               // 2048
    const long long PA  = (long long)BQ * SQ * HQ;
    const long long PA3 = (long long)BQ * SQ * H3;
    const long long PF  = (long long)BQ * SQ * FFQ;
    const long long PW  = (long long)LQ * HQ * HQ;
    const long long PW3 = (long long)LQ * HQ * H3;
    const long long PW1 = (long long)LQ * HQ * FFQ;
    const long long PFC = (long long)VQ * HQ;

    const int SM_T128 = 3 * (2 * 128 * 80 + 2 * 32 * (128 * 2 + 16));  // 113664 (3 stages)
    const int SM_FLASH = 2 * 4 * 64 * 144;                             // 73728

    cudaFuncSetAttribute(mma_gemm<128, 128, 0>, cudaFuncAttributeMaxDynamicSharedMemorySize, SM_T128);
    cudaFuncSetAttribute(mma_gemm<128, 128, 1>, cudaFuncAttributeMaxDynamicSharedMemorySize, SM_T128);
    cudaFuncSetAttribute(mma_gemm<128, 128, 2>, cudaFuncAttributeMaxDynamicSharedMemorySize, SM_T128);
    cudaFuncSetAttribute(mma_gemm<128, 128, 3>, cudaFuncAttributeMaxDynamicSharedMemorySize, SM_T128);
    cudaFuncSetAttribute(flash_kernel, cudaFuncAttributeMaxDynamicSharedMemorySize, SM_FLASH);

    // one-time weight conversions (part of the graph)
    split_qkv_kernel<<<(int)(PW3 / 1024), 256>>>(Wq, Wk, Wv, wqkv, PW3);
    concat_bias_kernel<<<(LQ * H3) / 256, 256>>>(bq, bk, bv, bqkv);
    split_kernel<<<(int)(PW  / 1024), 256>>>(Wo,  wos, PW);
    split_kernel<<<(int)(PW1 / 1024), 256>>>(W1,  w1s, PW1);
    split_kernel<<<(int)(PW1 / 1024), 256>>>(W2,  w2s, PW1);
    split_kernel<<<(int)(PFC / 1024), 256>>>(fcw, fws, PFC);

    embed_kernel<<<(M * HQ) / 512, 256>>>(x, emb, h, hs, PA);

    for (int l = 0; l < LQ; l++) {
        const bf16*  wqkvl = wqkv + (long long)l * HQ * H3;
        const float* bqkvl = bqkv + (long long)l * H3;
        const bf16* wol = wos + (long long)l * HQ * HQ;   const float* bol = bo + (long long)l * HQ;
        const bf16* w1l = w1s + (long long)l * HQ * FFQ;  const float* b1l = b1 + (long long)l * FFQ;
        const bf16* w2l = w2s + (long long)l * FFQ * HQ;  const float* b2l = b2 + (long long)l * HQ;

        // merged QKV: [2048,1024] @ [1024,3072] + bias -> split qkv buffer (384 CTAs)
        mma_gemm<128, 128, 2><<<dim3(M / 128, H3 / 128), 256, SM_T128>>>(
            hs, PA, wqkvl, PW3, bqkvl, nullptr, qkvs, PA3, HQ, HQ, H3, H3);

        // fused attention: scores + softmax + PV (reads merged qkv, stride H3)
        flash_kernel<<<dim3(SQ / 128, BQ * NHQ), 256, SM_FLASH>>>(qkvs, os, PA3, PA);

        // out projection + bias + residual(h) -> fp32 tt
        mma_gemm<128, 128, 1><<<dim3(M / 128, HQ / 128), 256, SM_T128>>>(
            os, PA, wol, PW, bol, h, tt, 0, HQ, HQ, HQ, HQ);
        ln_kernel<<<M, 256>>>(tt, ln1g + (long long)l * HQ, ln1b + (long long)l * HQ, h, hs, PA);

        // FFN
        mma_gemm<128, 128, 3><<<dim3(M / 128, FFQ / 128), 256, SM_T128>>>(
            hs, PA, w1l, PW1, b1l, nullptr, fs, PF, HQ, HQ, FFQ, FFQ);
        mma_gemm<128, 128, 1><<<dim3(M / 128, HQ / 128), 256, SM_T128>>>(
            fs, PF, w2l, PW1, b2l, h, tt, 0, FFQ, FFQ, HQ, HQ);
        ln_kernel<<<M, 256>>>(tt, ln2g + (long long)l * HQ, ln2b + (long long)l * HQ, h, hs, PA);
    }

    // final FC: [2048,1024] @ [1024,32000] + bias -> fp32 out
    mma_gemm<128, 128, 0><<<dim3(M / 128, VQ / 128), 256, SM_T128>>>(
        hs, PA, fws, PFC, fcb, nullptr, out, 0, HQ, HQ, VQ, VQ);
}